// round 1
// baseline (speedup 1.0000x reference)
#include <cuda_runtime.h>
#include <cuda_bf16.h>
#include <math.h>

// ---------------- problem constants ----------------
#define SEQ   2048
#define HID   2048
#define NH    16
#define NKV   2
#define HD    256
#define MAXS  4096
#define RD    64
#define GROUPS 8          // NH / NKV
#define ATT_SCALE 0.0625f // HD^-0.5
#define EPSV  1e-6f

// ---------------- scratch (static device globals; no allocs) ----------------
__device__ float g_qg   [(size_t)SEQ * 2 * NH * HD];   // 2048 x 8192  (q | gate interleaved per head)
__device__ float g_kproj[(size_t)SEQ * NKV * HD];      // 2048 x 512
__device__ float g_vproj[(size_t)SEQ * NKV * HD];      // 2048 x 512
__device__ float g_q    [(size_t)NH * SEQ * HD];       // [h][s][d]
__device__ float g_scores[(size_t)NH * SEQ * SEQ];     // [h][q][k]  (256 MB)
__device__ float g_attn [(size_t)NH * SEQ * HD];       // [h][s][d]
__device__ float g_gated[(size_t)SEQ * NH * HD];       // [s][h*HD+d]

// ---------------- generic tiled SGEMM ----------------
// C[m,n] = alpha * sum_k A[m,k] * B(k,n)
//   BT=true : B stored [N,K] k-inner (i.e. C = A * B^T), ldb = row stride of B
//   BT=false: B stored [K,N] n-inner (plain NN), ldb = row stride of B
// mode 0: plain. mode 1: causal block skip (square scores). mode 2: causal K-limit (PV).
// Per-z offsets: A += bz*sA ; B += (bz/bDiv)*sB ; C += bz*sC
#define BM 128
#define BN 128
#define BK 8
#define TM 8
#define TN 8

template<bool BT>
__global__ __launch_bounds__(256)
void gemm_kernel(const float* __restrict__ A, const float* __restrict__ B,
                 float* __restrict__ C,
                 int M, int N, int K, int lda, int ldb, int ldc,
                 long long sA, long long sB, long long sC, int bDiv,
                 float alpha, int mode)
{
    const int bx = blockIdx.x, by = blockIdx.y, bz = blockIdx.z;
    if (mode == 1 && bx * BN >= by * BM + BM) return;   // fully above diagonal
    const int Keff = (mode == 2) ? min(K, (by + 1) * BM) : K;

    A += (long long)bz * sA;
    B += (long long)(bz / bDiv) * sB;
    C += (long long)bz * sC;

    __shared__ float As[BK][BM];
    __shared__ float Bs[BK][BN];

    const int tid = threadIdx.x;
    const int tx = tid & 15;          // 0..15  -> col group
    const int ty = tid >> 4;          // 0..15  -> row group

    float acc[TM][TN];
    #pragma unroll
    for (int i = 0; i < TM; ++i)
        #pragma unroll
        for (int j = 0; j < TN; ++j) acc[i][j] = 0.f;

    // load lanes
    const int aRow = tid >> 1;            // 0..127
    const int aK   = (tid & 1) * 4;       // 0 or 4
    const int bR   = tid >> 5;            // 0..7   (NN)
    const int bC   = (tid & 31) * 4;      // 0..124 (NN)

    for (int kt = 0; kt < Keff; kt += BK) {
        // A tile (k-inner)
        float4 av = *reinterpret_cast<const float4*>(
            &A[(size_t)(by * BM + aRow) * lda + kt + aK]);
        As[aK + 0][aRow] = av.x;
        As[aK + 1][aRow] = av.y;
        As[aK + 2][aRow] = av.z;
        As[aK + 3][aRow] = av.w;

        if (BT) {
            float4 bv = *reinterpret_cast<const float4*>(
                &B[(size_t)(bx * BN + aRow) * ldb + kt + aK]);
            Bs[aK + 0][aRow] = bv.x;
            Bs[aK + 1][aRow] = bv.y;
            Bs[aK + 2][aRow] = bv.z;
            Bs[aK + 3][aRow] = bv.w;
        } else {
            float4 bv = *reinterpret_cast<const float4*>(
                &B[(size_t)(kt + bR) * ldb + bx * BN + bC]);
            *reinterpret_cast<float4*>(&Bs[bR][bC]) = bv;
        }
        __syncthreads();

        #pragma unroll
        for (int kk = 0; kk < BK; ++kk) {
            float a[TM], b[TN];
            float4 a0 = *reinterpret_cast<const float4*>(&As[kk][ty * TM]);
            float4 a1 = *reinterpret_cast<const float4*>(&As[kk][ty * TM + 4]);
            float4 b0 = *reinterpret_cast<const float4*>(&Bs[kk][tx * TN]);
            float4 b1 = *reinterpret_cast<const float4*>(&Bs[kk][tx * TN + 4]);
            a[0]=a0.x; a[1]=a0.y; a[2]=a0.z; a[3]=a0.w;
            a[4]=a1.x; a[5]=a1.y; a[6]=a1.z; a[7]=a1.w;
            b[0]=b0.x; b[1]=b0.y; b[2]=b0.z; b[3]=b0.w;
            b[4]=b1.x; b[5]=b1.y; b[6]=b1.z; b[7]=b1.w;
            #pragma unroll
            for (int i = 0; i < TM; ++i)
                #pragma unroll
                for (int j = 0; j < TN; ++j)
                    acc[i][j] = fmaf(a[i], b[j], acc[i][j]);
        }
        __syncthreads();
    }

    #pragma unroll
    for (int i = 0; i < TM; ++i) {
        size_t row = (size_t)(by * BM + ty * TM + i);
        float4 v0, v1;
        v0.x = acc[i][0] * alpha; v0.y = acc[i][1] * alpha;
        v0.z = acc[i][2] * alpha; v0.w = acc[i][3] * alpha;
        v1.x = acc[i][4] * alpha; v1.y = acc[i][5] * alpha;
        v1.z = acc[i][6] * alpha; v1.w = acc[i][7] * alpha;
        float* cp = &C[row * ldc + bx * BN + tx * TN];
        *reinterpret_cast<float4*>(cp)     = v0;
        *reinterpret_cast<float4*>(cp + 4) = v1;
    }
}

// ---------------- RMSNorm + RoPE for Q ----------------
// grid (SEQ, NH), 256 threads. in: g_qg[s, h*512 + d]. out: g_q[h][s][d]
__global__ __launch_bounds__(256)
void q_norm_rope_kernel(const float* __restrict__ qg,
                        const float* __restrict__ cosb,
                        const float* __restrict__ sinb,
                        const float* __restrict__ qw,
                        float* __restrict__ qout)
{
    const int s = blockIdx.x, h = blockIdx.y, d = threadIdx.x;
    float x = qg[(size_t)s * (2 * NH * HD) + h * (2 * HD) + d];
    __shared__ float red[256];
    __shared__ float xs[256];
    red[d] = x * x;
    __syncthreads();
    #pragma unroll
    for (int st = 128; st > 0; st >>= 1) {
        if (d < st) red[d] += red[d + st];
        __syncthreads();
    }
    float r = rsqrtf(red[0] * (1.f / HD) + EPSV);
    float xn = x * r * (1.f + qw[d]);
    xs[d] = xn;
    __syncthreads();
    float o = xn;
    if (d < RD) {
        float rot = (d < RD / 2) ? -xs[d + RD / 2] : xs[d - RD / 2];
        o = xn * cosb[(size_t)s * RD + d] + rot * sinb[(size_t)s * RD + d];
    }
    qout[((size_t)h * SEQ + s) * HD + d] = o;
}

// ---------------- RMSNorm + RoPE for K, write K/V caches ----------------
// grid (SEQ, NKV), 256 threads.
__global__ __launch_bounds__(256)
void kv_norm_rope_kernel(const float* __restrict__ kp,
                         const float* __restrict__ vp,
                         const float* __restrict__ cosb,
                         const float* __restrict__ sinb,
                         const float* __restrict__ kw,
                         float* __restrict__ kcache,
                         float* __restrict__ vcache)
{
    const int s = blockIdx.x, kv = blockIdx.y, d = threadIdx.x;
    float x = kp[(size_t)s * (NKV * HD) + kv * HD + d];
    __shared__ float red[256];
    __shared__ float xs[256];
    red[d] = x * x;
    __syncthreads();
    #pragma unroll
    for (int st = 128; st > 0; st >>= 1) {
        if (d < st) red[d] += red[d + st];
        __syncthreads();
    }
    float r = rsqrtf(red[0] * (1.f / HD) + EPSV);
    float xn = x * r * (1.f + kw[d]);
    xs[d] = xn;
    __syncthreads();
    float o = xn;
    if (d < RD) {
        float rot = (d < RD / 2) ? -xs[d + RD / 2] : xs[d - RD / 2];
        o = xn * cosb[(size_t)s * RD + d] + rot * sinb[(size_t)s * RD + d];
    }
    size_t base = ((size_t)kv * MAXS + s) * HD + d;
    kcache[base] = o;
    vcache[base] = vp[(size_t)s * (NKV * HD) + kv * HD + d];
}

// ---------------- zero pad of caches rows SEQ..MAXS ----------------
__global__ void zero_pad_kernel(float* __restrict__ kcache, float* __restrict__ vcache)
{
    size_t idx = (size_t)blockIdx.x * blockDim.x + threadIdx.x;
    const size_t per_kv = (size_t)(MAXS - SEQ) * HD;      // 524288
    const size_t total = (size_t)NKV * per_kv;            // 1048576
    if (idx >= total) return;
    size_t kv = idx / per_kv;
    size_t rem = idx - kv * per_kv;
    size_t off = kv * (size_t)MAXS * HD + (size_t)SEQ * HD + rem;
    kcache[off] = 0.f;
    vcache[off] = 0.f;
}

// ---------------- causal row softmax ----------------
// grid (SEQ, NH). Normalizes row [0..i], zeros (i, blockAlignedEnd).
__global__ __launch_bounds__(256)
void softmax_kernel(float* __restrict__ scores)
{
    const int i = blockIdx.x, h = blockIdx.y, tid = threadIdx.x;
    float* row = scores + ((size_t)h * SEQ + i) * SEQ;
    const int n = i + 1;
    __shared__ float red[256];

    float m = -1e30f;
    for (int j = tid; j < n; j += 256) m = fmaxf(m, row[j]);
    red[tid] = m;
    __syncthreads();
    #pragma unroll
    for (int st = 128; st > 0; st >>= 1) {
        if (tid < st) red[tid] = fmaxf(red[tid], red[tid + st]);
        __syncthreads();
    }
    m = red[0];
    __syncthreads();

    float sum = 0.f;
    for (int j = tid; j < n; j += 256) {
        float e = __expf(row[j] - m);
        row[j] = e;
        sum += e;
    }
    red[tid] = sum;
    __syncthreads();
    #pragma unroll
    for (int st = 128; st > 0; st >>= 1) {
        if (tid < st) red[tid] += red[tid + st];
        __syncthreads();
    }
    float inv = 1.f / red[0];
    for (int j = tid; j < n; j += 256) row[j] *= inv;

    // zero the tail of this row up to its 128-aligned block end (read by PV GEMM)
    const int end = ((i >> 7) + 1) << 7;
    for (int j = n + tid; j < end; j += 256) row[j] = 0.f;
}

// ---------------- gating: g_gated[s, h*HD+d] = attn * sigmoid(gate) ----------------
__global__ void gate_kernel(const float* __restrict__ attn,
                            const float* __restrict__ qg,
                            float* __restrict__ gated)
{
    size_t idx = (size_t)blockIdx.x * blockDim.x + threadIdx.x;
    const size_t total = (size_t)SEQ * NH * HD;
    if (idx >= total) return;
    int s = (int)(idx >> 12);           // / 4096
    int r = (int)(idx & 4095);
    int h = r >> 8;
    int d = r & 255;
    float a = attn[((size_t)h * SEQ + s) * HD + d];
    float g = qg[(size_t)s * (2 * NH * HD) + h * (2 * HD) + HD + d];
    gated[idx] = a * (1.f / (1.f + __expf(-g)));
}

// ---------------- launch ----------------
extern "C" void kernel_launch(void* const* d_in, const int* in_sizes, int n_in,
                              void* d_out, int out_size)
{
    const float* hidden = (const float*)d_in[0];
    const float* cosb   = (const float*)d_in[1];
    const float* sinb   = (const float*)d_in[2];
    const float* q_w    = (const float*)d_in[3];
    const float* k_w    = (const float*)d_in[4];
    const float* v_w    = (const float*)d_in[5];
    const float* o_w    = (const float*)d_in[6];
    const float* qnw    = (const float*)d_in[7];
    const float* knw    = (const float*)d_in[8];

    float* hidden_out = (float*)d_out;                                  // 2048*2048
    float* kcache = hidden_out + (size_t)SEQ * HID;                     // 2*4096*256
    float* vcache = kcache + (size_t)NKV * MAXS * HD;

    float *qg, *kp, *vp, *q, *sc, *at, *gt;
    cudaGetSymbolAddress((void**)&qg, g_qg);
    cudaGetSymbolAddress((void**)&kp, g_kproj);
    cudaGetSymbolAddress((void**)&vp, g_vproj);
    cudaGetSymbolAddress((void**)&q,  g_q);
    cudaGetSymbolAddress((void**)&sc, g_scores);
    cudaGetSymbolAddress((void**)&at, g_attn);
    cudaGetSymbolAddress((void**)&gt, g_gated);

    dim3 blk(256);

    // 1) QG = hidden @ q_proj_w^T   [2048 x 8192]
    gemm_kernel<true><<<dim3(8192 / BN, SEQ / BM, 1), blk>>>(
        hidden, q_w, qg, SEQ, 2 * NH * HD, HID, HID, HID, 2 * NH * HD,
        0, 0, 0, 1, 1.f, 0);
    // 2) K = hidden @ k_proj_w^T    [2048 x 512]
    gemm_kernel<true><<<dim3(512 / BN, SEQ / BM, 1), blk>>>(
        hidden, k_w, kp, SEQ, NKV * HD, HID, HID, HID, NKV * HD,
        0, 0, 0, 1, 1.f, 0);
    // 3) V = hidden @ v_proj_w^T    [2048 x 512]
    gemm_kernel<true><<<dim3(512 / BN, SEQ / BM, 1), blk>>>(
        hidden, v_w, vp, SEQ, NKV * HD, HID, HID, HID, NKV * HD,
        0, 0, 0, 1, 1.f, 0);

    // 4) Q RMSNorm + RoPE -> g_q[h][s][d]
    q_norm_rope_kernel<<<dim3(SEQ, NH), blk>>>(qg, cosb, sinb, qnw, q);
    // 5) K RMSNorm + RoPE -> kcache ; V -> vcache
    kv_norm_rope_kernel<<<dim3(SEQ, NKV), blk>>>(kp, vp, cosb, sinb, knw, kcache, vcache);
    // 6) zero-pad cache rows SEQ..MAXS
    zero_pad_kernel<<<(int)(((size_t)NKV * (MAXS - SEQ) * HD + 255) / 256), blk>>>(kcache, vcache);

    // 7) scores[h] = (Q[h] @ Kc[h/8]^T) * SCALE  (causal block-skip)
    gemm_kernel<true><<<dim3(SEQ / BN, SEQ / BM, NH), blk>>>(
        q, kcache, sc, SEQ, SEQ, HD, HD, HD, SEQ,
        (long long)SEQ * HD, (long long)MAXS * HD, (long long)SEQ * SEQ, GROUPS,
        ATT_SCALE, 1);

    // 8) causal softmax per row
    softmax_kernel<<<dim3(SEQ, NH), blk>>>(sc);

    // 9) attn[h] = P[h] @ Vc[h/8]   (causal K-limit), NN gemm
    gemm_kernel<false><<<dim3(HD / BN, SEQ / BM, NH), blk>>>(
        sc, vcache, at, SEQ, HD, SEQ, SEQ, HD, HD,
        (long long)SEQ * SEQ, (long long)MAXS * HD, (long long)SEQ * HD, GROUPS,
        1.f, 2);

    // 10) gating
    gate_kernel<<<(int)(((size_t)SEQ * NH * HD + 255) / 256), blk>>>(at, qg, gt);

    // 11) hidden_out = gated @ o_proj_w^T  [2048 x 2048], K = 4096
    gemm_kernel<true><<<dim3(HID / BN, SEQ / BM, 1), blk>>>(
        gt, o_w, hidden_out, SEQ, HID, NH * HD, NH * HD, NH * HD, HID,
        0, 0, 0, 1, 1.f, 0);
}

// round 3
// speedup vs baseline: 2.7093x; 2.7093x over previous
#include <cuda_runtime.h>
#include <cuda_bf16.h>
#include <cstdint>
#include <math.h>

// ---------------- problem constants ----------------
#define SEQ   2048
#define HID   2048
#define NH    16
#define NKV   2
#define HD    256
#define MAXS  4096
#define RD    64
#define GROUPS 8
#define ATT_SCALE 0.0625f
#define EPSV  1e-6f

typedef __nv_bfloat16 bf16;

// ---------------- scratch (static device globals; no allocs) ----------------
__device__ __align__(1024) float g_qg   [(size_t)SEQ * 2 * NH * HD];
__device__ __align__(1024) float g_kproj[(size_t)SEQ * NKV * HD];
__device__ __align__(1024) float g_vproj[(size_t)SEQ * NKV * HD];
__device__ __align__(1024) float g_scores[(size_t)NH * SEQ * SEQ];   // 256 MB
__device__ __align__(1024) float g_attn [(size_t)NH * SEQ * HD];

__device__ __align__(1024) bf16 g_hid_h[(size_t)SEQ * HID],      g_hid_l[(size_t)SEQ * HID];
__device__ __align__(1024) bf16 g_qw_h [(size_t)2*NH*HD * HID],  g_qw_l [(size_t)2*NH*HD * HID];
__device__ __align__(1024) bf16 g_kw_h [(size_t)NKV*HD * HID],   g_kw_l [(size_t)NKV*HD * HID];
__device__ __align__(1024) bf16 g_vw_h [(size_t)NKV*HD * HID],   g_vw_l [(size_t)NKV*HD * HID];
__device__ __align__(1024) bf16 g_ow_h [(size_t)HID * NH*HD],    g_ow_l [(size_t)HID * NH*HD];
__device__ __align__(1024) bf16 g_q_h  [(size_t)NH*SEQ*HD],      g_q_l  [(size_t)NH*SEQ*HD];
__device__ __align__(1024) bf16 g_k_h  [(size_t)NKV*SEQ*HD],     g_k_l  [(size_t)NKV*SEQ*HD];
__device__ __align__(1024) bf16 g_vT_h [(size_t)NKV*HD*SEQ],     g_vT_l [(size_t)NKV*HD*SEQ];
__device__ __align__(1024) bf16 g_p_h  [(size_t)NH*SEQ*SEQ],     g_p_l  [(size_t)NH*SEQ*SEQ];
__device__ __align__(1024) bf16 g_gt_h [(size_t)SEQ * NH*HD],    g_gt_l [(size_t)SEQ * NH*HD];

// ---------------- PTX helpers (baseline PTX only; no tcgen05/'a' features) ----
__device__ __forceinline__ uint32_t smem_u32(const void* p) {
    uint32_t a;
    asm("{ .reg .u64 t; cvta.to.shared.u64 t, %1; cvt.u32.u64 %0, t; }" : "=r"(a) : "l"(p));
    return a;
}
#define CP_ASYNC16(dst, src) \
    asm volatile("cp.async.cg.shared.global [%0], [%1], 16;" :: "r"(dst), "l"(src) : "memory")
#define CP_COMMIT() asm volatile("cp.async.commit_group;" ::: "memory")
#define CP_WAIT(n)  asm volatile("cp.async.wait_group %0;" :: "n"(n) : "memory")

#define LDSM_X4(r0, r1, r2, r3, addr) \
    asm volatile("ldmatrix.sync.aligned.m8n8.x4.shared.b16 {%0,%1,%2,%3}, [%4];" \
        : "=r"(r0), "=r"(r1), "=r"(r2), "=r"(r3) : "r"(addr))

#define MMA16816(d, a, b0v, b1v) \
    asm volatile("mma.sync.aligned.m16n8k16.row.col.f32.bf16.bf16.f32 " \
        "{%0,%1,%2,%3}, {%4,%5,%6,%7}, {%8,%9}, {%0,%1,%2,%3};" \
        : "+f"((d)[0]), "+f"((d)[1]), "+f"((d)[2]), "+f"((d)[3]) \
        : "r"((a)[0]), "r"((a)[1]), "r"((a)[2]), "r"((a)[3]), "r"(b0v), "r"(b1v))

// ---------------- split-bf16 HMMA GEMM ----------------
// C[M,N] = alpha * (Ah+Al)[M,K] * (Bh+Bl)[N,K]^T  (both K-major bf16, fp32 out)
// mode 0 plain; 1 causal block-skip (BM==BN==128); 2 causal K-limit.
// 512 threads, CTA tile 128x128, K-chunk 64, double-buffered cp.async.
#define GSMEM 131072

__global__ __launch_bounds__(512, 1)
void gemm_hmma(const bf16* __restrict__ Ah, const bf16* __restrict__ Al,
               const bf16* __restrict__ Bh, const bf16* __restrict__ Bl,
               float* __restrict__ C,
               int K, int lda, int ldb, int ldc,
               long long sA, long long sB, long long sC, int bDiv,
               float alpha, int mode)
{
    const int bx = blockIdx.x, by = blockIdx.y, bz = blockIdx.z;
    if (mode == 1 && bx > by) return;
    const int Keff = (mode == 2) ? min(K, (by + 1) * 128) : K;
    const int nch = Keff >> 6;

    extern __shared__ char smem[];
    const uint32_t sb = smem_u32(smem);

    const bf16* srcs[4] = { Ah + (size_t)bz * sA, Al + (size_t)bz * sA,
                            Bh + (size_t)(bz / bDiv) * sB, Bl + (size_t)(bz / bDiv) * sB };
    const int lds[4] = { lda, lda, ldb, ldb };
    const int rb [4] = { by * 128, by * 128, bx * 128, bx * 128 };

    const int tid = threadIdx.x, lane = tid & 31, wid = tid >> 5;
    const int wm = wid >> 2, wn = wid & 3;

    float acc[2][4][4];
    #pragma unroll
    for (int mt = 0; mt < 2; ++mt)
        #pragma unroll
        for (int nt = 0; nt < 4; ++nt)
            #pragma unroll
            for (int r = 0; r < 4; ++r) acc[mt][nt][r] = 0.f;

    // ---- cp.async issue of one 64-wide K chunk into buf (ch&1) ----
    auto issue = [&](int ch) {
        const uint32_t dbase = sb + (uint32_t)(ch & 1) * 65536u;
        const int kt = ch << 6;
        #pragma unroll
        for (int p = 0; p < 4; ++p) {
            #pragma unroll
            for (int i = 0; i < 2; ++i) {
                const int u = tid + i * 512;          // 0..1023
                const int r = u >> 3, c = u & 7;
                const bf16* s = srcs[p] + (size_t)(rb[p] + r) * lds[p] + kt + c * 8;
                const uint32_t d = dbase + (uint32_t)(p * 16384 + r * 128 +
                                   ((c * 16) ^ ((r & 7) << 4)));
                CP_ASYNC16(d, (const void*)s);
            }
        }
        CP_COMMIT();
    };

    issue(0);
    for (int ch = 0; ch < nch; ++ch) {
        if (ch + 1 < nch) { issue(ch + 1); CP_WAIT(1); }
        else              { CP_WAIT(0); }
        __syncthreads();

        const uint32_t b0 = sb + (uint32_t)(ch & 1) * 65536u;

        #pragma unroll
        for (int ks = 0; ks < 4; ++ks) {
            uint32_t ah[2][4], alr[2][4], bh[2][4], blr[2][4];
            const uint32_t colk = (uint32_t)(ks * 32 + ((lane >> 4) << 4));
            #pragma unroll
            for (int mt = 0; mt < 2; ++mt) {
                const int row = wm * 32 + mt * 16 + (lane & 15);
                const uint32_t a0 = b0 + (uint32_t)(row * 128) + (colk ^ ((row & 7) << 4));
                LDSM_X4(ah [mt][0], ah [mt][1], ah [mt][2], ah [mt][3], a0);
                LDSM_X4(alr[mt][0], alr[mt][1], alr[mt][2], alr[mt][3], a0 + 16384u);
            }
            #pragma unroll
            for (int pr = 0; pr < 2; ++pr) {
                const int row = wn * 32 + pr * 16 + (lane & 15);
                const uint32_t a0 = b0 + 32768u + (uint32_t)(row * 128) + (colk ^ ((row & 7) << 4));
                LDSM_X4(bh [pr][0], bh [pr][1], bh [pr][2], bh [pr][3], a0);
                LDSM_X4(blr[pr][0], blr[pr][1], blr[pr][2], blr[pr][3], a0 + 16384u);
            }
            #pragma unroll
            for (int mt = 0; mt < 2; ++mt) {
                #pragma unroll
                for (int nt = 0; nt < 4; ++nt) {
                    const uint32_t hb0 = bh [nt >> 1][nt & 1], hb1 = bh [nt >> 1][(nt & 1) + 2];
                    const uint32_t lb0 = blr[nt >> 1][nt & 1], lb1 = blr[nt >> 1][(nt & 1) + 2];
                    MMA16816(acc[mt][nt], ah [mt], hb0, hb1);   // hi*hi
                    MMA16816(acc[mt][nt], ah [mt], lb0, lb1);   // hi*lo
                    MMA16816(acc[mt][nt], alr[mt], hb0, hb1);   // lo*hi
                }
            }
        }
        __syncthreads();
    }

    // ---- epilogue: direct float2 stores ----
    float* pC = C + (size_t)bz * sC;
    #pragma unroll
    for (int mt = 0; mt < 2; ++mt) {
        #pragma unroll
        for (int nt = 0; nt < 4; ++nt) {
            const int row = by * 128 + wm * 32 + mt * 16 + (lane >> 2);
            const int col = bx * 128 + wn * 32 + nt * 8 + (lane & 3) * 2;
            float2 v0 = { acc[mt][nt][0] * alpha, acc[mt][nt][1] * alpha };
            float2 v1 = { acc[mt][nt][2] * alpha, acc[mt][nt][3] * alpha };
            *reinterpret_cast<float2*>(&pC[(size_t)row * ldc + col])       = v0;
            *reinterpret_cast<float2*>(&pC[(size_t)(row + 8) * ldc + col]) = v1;
        }
    }
}

// ---------------- fp32 -> (hi, lo) bf16 split ----------------
__global__ void split_kernel(const float* __restrict__ x, bf16* __restrict__ hi,
                             bf16* __restrict__ lo, size_t n)
{
    size_t i = (size_t)blockIdx.x * blockDim.x + threadIdx.x;
    if (i >= n) return;
    float v = x[i];
    bf16 h = __float2bfloat16(v);
    hi[i] = h;
    lo[i] = __float2bfloat16(v - __bfloat162float(h));
}

// ---------------- RMSNorm + RoPE for Q -> split planes ----------------
__global__ __launch_bounds__(256)
void q_norm_rope_kernel(const float* __restrict__ qg,
                        const float* __restrict__ cosb, const float* __restrict__ sinb,
                        const float* __restrict__ qw,
                        bf16* __restrict__ qh, bf16* __restrict__ ql)
{
    const int s = blockIdx.x, h = blockIdx.y, d = threadIdx.x;
    float x = qg[(size_t)s * (2 * NH * HD) + h * (2 * HD) + d];
    __shared__ float red[256];
    __shared__ float xs[256];
    red[d] = x * x;
    __syncthreads();
    #pragma unroll
    for (int st = 128; st > 0; st >>= 1) { if (d < st) red[d] += red[d + st]; __syncthreads(); }
    float r = rsqrtf(red[0] * (1.f / HD) + EPSV);
    float xn = x * r * (1.f + qw[d]);
    xs[d] = xn;
    __syncthreads();
    float o = xn;
    if (d < RD) {
        float rot = (d < RD / 2) ? -xs[d + RD / 2] : xs[d - RD / 2];
        o = xn * cosb[(size_t)s * RD + d] + rot * sinb[(size_t)s * RD + d];
    }
    size_t idx = ((size_t)h * SEQ + s) * HD + d;
    bf16 hv = __float2bfloat16(o);
    qh[idx] = hv;
    ql[idx] = __float2bfloat16(o - __bfloat162float(hv));
}

// ---------------- RMSNorm + RoPE for K; caches + split planes ----------------
__global__ __launch_bounds__(256)
void kv_norm_rope_kernel(const float* __restrict__ kp, const float* __restrict__ vp,
                         const float* __restrict__ cosb, const float* __restrict__ sinb,
                         const float* __restrict__ kw,
                         float* __restrict__ kcache, float* __restrict__ vcache,
                         bf16* __restrict__ kh, bf16* __restrict__ kl,
                         bf16* __restrict__ vTh, bf16* __restrict__ vTl)
{
    const int s = blockIdx.x, kv = blockIdx.y, d = threadIdx.x;
    float x = kp[(size_t)s * (NKV * HD) + kv * HD + d];
    __shared__ float red[256];
    __shared__ float xs[256];
    red[d] = x * x;
    __syncthreads();
    #pragma unroll
    for (int st = 128; st > 0; st >>= 1) { if (d < st) red[d] += red[d + st]; __syncthreads(); }
    float r = rsqrtf(red[0] * (1.f / HD) + EPSV);
    float xn = x * r * (1.f + kw[d]);
    xs[d] = xn;
    __syncthreads();
    float o = xn;
    if (d < RD) {
        float rot = (d < RD / 2) ? -xs[d + RD / 2] : xs[d - RD / 2];
        o = xn * cosb[(size_t)s * RD + d] + rot * sinb[(size_t)s * RD + d];
    }
    float v = vp[(size_t)s * (NKV * HD) + kv * HD + d];
    size_t cidx = ((size_t)kv * MAXS + s) * HD + d;
    kcache[cidx] = o;
    vcache[cidx] = v;
    size_t kidx = ((size_t)kv * SEQ + s) * HD + d;
    bf16 khv = __float2bfloat16(o);
    kh[kidx] = khv;
    kl[kidx] = __float2bfloat16(o - __bfloat162float(khv));
    size_t vidx = ((size_t)kv * HD + d) * SEQ + s;   // transposed
    bf16 vhv = __float2bfloat16(v);
    vTh[vidx] = vhv;
    vTl[vidx] = __float2bfloat16(v - __bfloat162float(vhv));
}

// ---------------- zero pad caches rows SEQ..MAXS ----------------
__global__ void zero_pad_kernel(float* __restrict__ kcache, float* __restrict__ vcache)
{
    size_t idx = (size_t)blockIdx.x * blockDim.x + threadIdx.x;
    const size_t per_kv = (size_t)(MAXS - SEQ) * HD;
    if (idx >= (size_t)NKV * per_kv) return;
    size_t kv = idx / per_kv, rem = idx - kv * per_kv;
    size_t off = kv * (size_t)MAXS * HD + (size_t)SEQ * HD + rem;
    kcache[off] = 0.f;
    vcache[off] = 0.f;
}

// ---------------- causal softmax -> split P planes ----------------
__global__ __launch_bounds__(256)
void softmax_kernel(float* __restrict__ scores, bf16* __restrict__ ph, bf16* __restrict__ pl)
{
    const int i = blockIdx.x, h = blockIdx.y, tid = threadIdx.x;
    float* row = scores + ((size_t)h * SEQ + i) * SEQ;
    bf16* prh = ph + ((size_t)h * SEQ + i) * SEQ;
    bf16* prl = pl + ((size_t)h * SEQ + i) * SEQ;
    const int n = i + 1;
    __shared__ float red[256];

    float m = -1e30f;
    for (int j = tid; j < n; j += 256) m = fmaxf(m, row[j]);
    red[tid] = m;
    __syncthreads();
    #pragma unroll
    for (int st = 128; st > 0; st >>= 1) { if (tid < st) red[tid] = fmaxf(red[tid], red[tid + st]); __syncthreads(); }
    m = red[0];
    __syncthreads();

    float sum = 0.f;
    for (int j = tid; j < n; j += 256) {
        float e = __expf(row[j] - m);
        row[j] = e;
        sum += e;
    }
    red[tid] = sum;
    __syncthreads();
    #pragma unroll
    for (int st = 128; st > 0; st >>= 1) { if (tid < st) red[tid] += red[tid + st]; __syncthreads(); }
    float inv = 1.f / red[0];

    for (int j = tid; j < n; j += 256) {
        float p = row[j] * inv;
        bf16 hv = __float2bfloat16(p);
        prh[j] = hv;
        prl[j] = __float2bfloat16(p - __bfloat162float(hv));
    }
    const int end = ((i >> 7) + 1) << 7;
    for (int j = n + tid; j < end; j += 256) { prh[j] = __float2bfloat16(0.f); prl[j] = __float2bfloat16(0.f); }
}

// ---------------- gating -> split planes ----------------
__global__ void gate_kernel(const float* __restrict__ attn, const float* __restrict__ qg,
                            bf16* __restrict__ gh, bf16* __restrict__ gl)
{
    size_t idx = (size_t)blockIdx.x * blockDim.x + threadIdx.x;
    if (idx >= (size_t)SEQ * NH * HD) return;
    int s = (int)(idx >> 12);
    int r = (int)(idx & 4095);
    int h = r >> 8, d = r & 255;
    float a = attn[((size_t)h * SEQ + s) * HD + d];
    float g = qg[(size_t)s * (2 * NH * HD) + h * (2 * HD) + HD + d];
    float o = a * (1.f / (1.f + __expf(-g)));
    bf16 hv = __float2bfloat16(o);
    gh[idx] = hv;
    gl[idx] = __float2bfloat16(o - __bfloat162float(hv));
}

// ---------------- launch ----------------
extern "C" void kernel_launch(void* const* d_in, const int* in_sizes, int n_in,
                              void* d_out, int out_size)
{
    const float* hidden = (const float*)d_in[0];
    const float* cosb   = (const float*)d_in[1];
    const float* sinb   = (const float*)d_in[2];
    const float* q_w    = (const float*)d_in[3];
    const float* k_w    = (const float*)d_in[4];
    const float* v_w    = (const float*)d_in[5];
    const float* o_w    = (const float*)d_in[6];
    const float* qnw    = (const float*)d_in[7];
    const float* knw    = (const float*)d_in[8];

    float* hidden_out = (float*)d_out;
    float* kcache = hidden_out + (size_t)SEQ * HID;
    float* vcache = kcache + (size_t)NKV * MAXS * HD;

    float *qg, *kp, *vp, *sc, *at;
    bf16 *hidh, *hidl, *qwh, *qwl, *kwh, *kwl, *vwh, *vwl, *owh, *owl;
    bf16 *qh, *ql, *kh, *kl, *vTh, *vTl, *ph, *pl, *gth, *gtl;
    cudaGetSymbolAddress((void**)&qg, g_qg);
    cudaGetSymbolAddress((void**)&kp, g_kproj);
    cudaGetSymbolAddress((void**)&vp, g_vproj);
    cudaGetSymbolAddress((void**)&sc, g_scores);
    cudaGetSymbolAddress((void**)&at, g_attn);
    cudaGetSymbolAddress((void**)&hidh, g_hid_h); cudaGetSymbolAddress((void**)&hidl, g_hid_l);
    cudaGetSymbolAddress((void**)&qwh, g_qw_h);   cudaGetSymbolAddress((void**)&qwl, g_qw_l);
    cudaGetSymbolAddress((void**)&kwh, g_kw_h);   cudaGetSymbolAddress((void**)&kwl, g_kw_l);
    cudaGetSymbolAddress((void**)&vwh, g_vw_h);   cudaGetSymbolAddress((void**)&vwl, g_vw_l);
    cudaGetSymbolAddress((void**)&owh, g_ow_h);   cudaGetSymbolAddress((void**)&owl, g_ow_l);
    cudaGetSymbolAddress((void**)&qh, g_q_h);     cudaGetSymbolAddress((void**)&ql, g_q_l);
    cudaGetSymbolAddress((void**)&kh, g_k_h);     cudaGetSymbolAddress((void**)&kl, g_k_l);
    cudaGetSymbolAddress((void**)&vTh, g_vT_h);   cudaGetSymbolAddress((void**)&vTl, g_vT_l);
    cudaGetSymbolAddress((void**)&ph, g_p_h);     cudaGetSymbolAddress((void**)&pl, g_p_l);
    cudaGetSymbolAddress((void**)&gth, g_gt_h);   cudaGetSymbolAddress((void**)&gtl, g_gt_l);

    cudaFuncSetAttribute(gemm_hmma, cudaFuncAttributeMaxDynamicSharedMemorySize, GSMEM);

    dim3 blk(256);
    dim3 gblk(512);
    auto nb = [](size_t n) { return (unsigned)((n + 255) / 256); };

    // split fp32 inputs into (hi, lo) bf16 planes
    split_kernel<<<nb((size_t)SEQ * HID), blk>>>(hidden, hidh, hidl, (size_t)SEQ * HID);
    split_kernel<<<nb((size_t)2*NH*HD * HID), blk>>>(q_w, qwh, qwl, (size_t)2*NH*HD * HID);
    split_kernel<<<nb((size_t)NKV*HD * HID), blk>>>(k_w, kwh, kwl, (size_t)NKV*HD * HID);
    split_kernel<<<nb((size_t)NKV*HD * HID), blk>>>(v_w, vwh, vwl, (size_t)NKV*HD * HID);
    split_kernel<<<nb((size_t)HID * NH*HD), blk>>>(o_w, owh, owl, (size_t)HID * NH*HD);

    // projections
    gemm_hmma<<<dim3(2*NH*HD/128, SEQ/128, 1), gblk, GSMEM>>>(
        hidh, hidl, qwh, qwl, qg, HID, HID, HID, 2*NH*HD, 0, 0, 0, 1, 1.f, 0);
    gemm_hmma<<<dim3(NKV*HD/128, SEQ/128, 1), gblk, GSMEM>>>(
        hidh, hidl, kwh, kwl, kp, HID, HID, HID, NKV*HD, 0, 0, 0, 1, 1.f, 0);
    gemm_hmma<<<dim3(NKV*HD/128, SEQ/128, 1), gblk, GSMEM>>>(
        hidh, hidl, vwh, vwl, vp, HID, HID, HID, NKV*HD, 0, 0, 0, 1, 1.f, 0);

    // norms + rope + caches
    q_norm_rope_kernel<<<dim3(SEQ, NH), blk>>>(qg, cosb, sinb, qnw, qh, ql);
    kv_norm_rope_kernel<<<dim3(SEQ, NKV), blk>>>(kp, vp, cosb, sinb, knw,
                                                 kcache, vcache, kh, kl, vTh, vTl);
    zero_pad_kernel<<<nb((size_t)NKV * (MAXS - SEQ) * HD), blk>>>(kcache, vcache);

    // scores = Q @ K^T * scale (causal block skip)
    gemm_hmma<<<dim3(SEQ/128, SEQ/128, NH), gblk, GSMEM>>>(
        qh, ql, kh, kl, sc, HD, HD, HD, SEQ,
        (long long)SEQ * HD, (long long)SEQ * HD, (long long)SEQ * SEQ, GROUPS,
        ATT_SCALE, 1);

    softmax_kernel<<<dim3(SEQ, NH), blk>>>(sc, ph, pl);

    // attn = P @ V (causal K limit); B = V^T [d][s]
    gemm_hmma<<<dim3(HD/128, SEQ/128, NH), gblk, GSMEM>>>(
        ph, pl, vTh, vTl, at, SEQ, SEQ, SEQ, HD,
        (long long)SEQ * SEQ, (long long)HD * SEQ, (long long)SEQ * HD, GROUPS,
        1.f, 2);

    gate_kernel<<<nb((size_t)SEQ * NH * HD), blk>>>(at, qg, gth, gtl);

    // hidden_out = gated @ o_w^T
    gemm_hmma<<<dim3(HID/128, SEQ/128, 1), gblk, GSMEM>>>(
        gth, gtl, owh, owl, hidden_out, NH*HD, NH*HD, NH*HD, HID, 0, 0, 0, 1, 1.f, 0);
}

// round 4
// speedup vs baseline: 3.1037x; 1.1456x over previous
#include <cuda_runtime.h>
#include <cuda_bf16.h>
#include <cstdint>
#include <math.h>

// ---------------- problem constants ----------------
#define SEQ   2048
#define HID   2048
#define NH    16
#define NKV   2
#define HD    256
#define MAXS  4096
#define RD    64
#define GROUPS 8
#define ATT_SCALE 0.0625f
#define EPSV  1e-6f
#define NQKV  9216        // 8192 (q|gate) + 512 (k) + 512 (v)

typedef __nv_bfloat16 bf16;

// ---------------- scratch (static device globals; no allocs) ----------------
__device__ __align__(1024) float g_qkv  [(size_t)SEQ * NQKV];        // fused proj out
__device__ __align__(1024) float g_scores[(size_t)NH * SEQ * SEQ];   // 256 MB
__device__ __align__(1024) float g_attn [(size_t)NH * SEQ * HD];

__device__ __align__(1024) bf16 g_hid_h[(size_t)SEQ * HID],      g_hid_l[(size_t)SEQ * HID];
__device__ __align__(1024) bf16 g_wqkv_h[(size_t)NQKV * HID],    g_wqkv_l[(size_t)NQKV * HID];
__device__ __align__(1024) bf16 g_ow_h [(size_t)HID * NH*HD],    g_ow_l [(size_t)HID * NH*HD];
__device__ __align__(1024) bf16 g_q_h  [(size_t)NH*SEQ*HD],      g_q_l  [(size_t)NH*SEQ*HD];
__device__ __align__(1024) bf16 g_k_h  [(size_t)NKV*SEQ*HD],     g_k_l  [(size_t)NKV*SEQ*HD];
__device__ __align__(1024) bf16 g_vT_h [(size_t)NKV*HD*SEQ],     g_vT_l [(size_t)NKV*HD*SEQ];
__device__ __align__(1024) bf16 g_p_h  [(size_t)NH*SEQ*SEQ],     g_p_l  [(size_t)NH*SEQ*SEQ];
__device__ __align__(1024) bf16 g_gt_h [(size_t)SEQ * NH*HD],    g_gt_l [(size_t)SEQ * NH*HD];

// ---------------- PTX helpers (baseline PTX only) ----------------
__device__ __forceinline__ uint32_t smem_u32(const void* p) {
    uint32_t a;
    asm("{ .reg .u64 t; cvta.to.shared.u64 t, %1; cvt.u32.u64 %0, t; }" : "=r"(a) : "l"(p));
    return a;
}
#define CP_ASYNC16(dst, src) \
    asm volatile("cp.async.cg.shared.global [%0], [%1], 16;" :: "r"(dst), "l"(src) : "memory")
#define CP_COMMIT() asm volatile("cp.async.commit_group;" ::: "memory")
#define CP_WAIT(n)  asm volatile("cp.async.wait_group %0;" :: "n"(n) : "memory")

#define LDSM_X4(r0, r1, r2, r3, addr) \
    asm volatile("ldmatrix.sync.aligned.m8n8.x4.shared.b16 {%0,%1,%2,%3}, [%4];" \
        : "=r"(r0), "=r"(r1), "=r"(r2), "=r"(r3) : "r"(addr))

#define MMA16816(d, a, b0v, b1v) \
    asm volatile("mma.sync.aligned.m16n8k16.row.col.f32.bf16.bf16.f32 " \
        "{%0,%1,%2,%3}, {%4,%5,%6,%7}, {%8,%9}, {%0,%1,%2,%3};" \
        : "+f"((d)[0]), "+f"((d)[1]), "+f"((d)[2]), "+f"((d)[3]) \
        : "r"((a)[0]), "r"((a)[1]), "r"((a)[2]), "r"((a)[3]), "r"(b0v), "r"(b1v))

// ---------------- split-bf16 HMMA GEMM ----------------
// C[M,N] = alpha * (Ah+Al)[M,K] * (Bh+Bl)[N,K]^T  (both K-major bf16, fp32 out)
// mode 0 plain; 1 causal block-skip; 2 causal K-limit.
#define GSMEM 131072

__global__ __launch_bounds__(512, 1)
void gemm_hmma(const bf16* __restrict__ Ah, const bf16* __restrict__ Al,
               const bf16* __restrict__ Bh, const bf16* __restrict__ Bl,
               float* __restrict__ C,
               int K, int lda, int ldb, int ldc,
               long long sA, long long sB, long long sC, int bDiv,
               float alpha, int mode)
{
    const int bx = blockIdx.x, by = blockIdx.y, bz = blockIdx.z;
    if (mode == 1 && bx > by) return;
    const int Keff = (mode == 2) ? min(K, (by + 1) * 128) : K;
    const int nch = Keff >> 6;

    extern __shared__ char smem[];
    const uint32_t sb = smem_u32(smem);

    const bf16* srcs[4] = { Ah + (size_t)bz * sA, Al + (size_t)bz * sA,
                            Bh + (size_t)(bz / bDiv) * sB, Bl + (size_t)(bz / bDiv) * sB };
    const int lds[4] = { lda, lda, ldb, ldb };
    const int rb [4] = { by * 128, by * 128, bx * 128, bx * 128 };

    const int tid = threadIdx.x, lane = tid & 31, wid = tid >> 5;
    const int wm = wid >> 2, wn = wid & 3;

    float acc[2][4][4];
    #pragma unroll
    for (int mt = 0; mt < 2; ++mt)
        #pragma unroll
        for (int nt = 0; nt < 4; ++nt)
            #pragma unroll
            for (int r = 0; r < 4; ++r) acc[mt][nt][r] = 0.f;

    auto issue = [&](int ch) {
        const uint32_t dbase = sb + (uint32_t)(ch & 1) * 65536u;
        const int kt = ch << 6;
        #pragma unroll
        for (int p = 0; p < 4; ++p) {
            #pragma unroll
            for (int i = 0; i < 2; ++i) {
                const int u = tid + i * 512;
                const int r = u >> 3, c = u & 7;
                const bf16* s = srcs[p] + (size_t)(rb[p] + r) * lds[p] + kt + c * 8;
                const uint32_t d = dbase + (uint32_t)(p * 16384 + r * 128 +
                                   ((c * 16) ^ ((r & 7) << 4)));
                CP_ASYNC16(d, (const void*)s);
            }
        }
        CP_COMMIT();
    };

    issue(0);
    for (int ch = 0; ch < nch; ++ch) {
        if (ch + 1 < nch) { issue(ch + 1); CP_WAIT(1); }
        else              { CP_WAIT(0); }
        __syncthreads();

        const uint32_t b0 = sb + (uint32_t)(ch & 1) * 65536u;

        #pragma unroll
        for (int ks = 0; ks < 4; ++ks) {
            uint32_t ah[2][4], alr[2][4], bh[2][4], blr[2][4];
            const uint32_t colk = (uint32_t)(ks * 32 + ((lane >> 4) << 4));
            #pragma unroll
            for (int mt = 0; mt < 2; ++mt) {
                const int row = wm * 32 + mt * 16 + (lane & 15);
                const uint32_t a0 = b0 + (uint32_t)(row * 128) + (colk ^ ((row & 7) << 4));
                LDSM_X4(ah [mt][0], ah [mt][1], ah [mt][2], ah [mt][3], a0);
                LDSM_X4(alr[mt][0], alr[mt][1], alr[mt][2], alr[mt][3], a0 + 16384u);
            }
            #pragma unroll
            for (int pr = 0; pr < 2; ++pr) {
                const int row = wn * 32 + pr * 16 + (lane & 15);
                const uint32_t a0 = b0 + 32768u + (uint32_t)(row * 128) + (colk ^ ((row & 7) << 4));
                LDSM_X4(bh [pr][0], bh [pr][1], bh [pr][2], bh [pr][3], a0);
                LDSM_X4(blr[pr][0], blr[pr][1], blr[pr][2], blr[pr][3], a0 + 16384u);
            }
            // term-outer: dependent MMAs on the same acc are 8 issues apart
            #pragma unroll
            for (int term = 0; term < 3; ++term) {
                #pragma unroll
                for (int mt = 0; mt < 2; ++mt) {
                    #pragma unroll
                    for (int nt = 0; nt < 4; ++nt) {
                        const uint32_t* af = (term == 2) ? alr[mt] : ah[mt];
                        const uint32_t b0v = (term == 1) ? blr[nt >> 1][nt & 1]
                                                         : bh [nt >> 1][nt & 1];
                        const uint32_t b1v = (term == 1) ? blr[nt >> 1][(nt & 1) + 2]
                                                         : bh [nt >> 1][(nt & 1) + 2];
                        MMA16816(acc[mt][nt], af, b0v, b1v);
                    }
                }
            }
        }
        __syncthreads();
    }

    float* pC = C + (size_t)bz * sC;
    #pragma unroll
    for (int mt = 0; mt < 2; ++mt) {
        #pragma unroll
        for (int nt = 0; nt < 4; ++nt) {
            const int row = by * 128 + wm * 32 + mt * 16 + (lane >> 2);
            const int col = bx * 128 + wn * 32 + nt * 8 + (lane & 3) * 2;
            float2 v0 = { acc[mt][nt][0] * alpha, acc[mt][nt][1] * alpha };
            float2 v1 = { acc[mt][nt][2] * alpha, acc[mt][nt][3] * alpha };
            *reinterpret_cast<float2*>(&pC[(size_t)row * ldc + col])       = v0;
            *reinterpret_cast<float2*>(&pC[(size_t)(row + 8) * ldc + col]) = v1;
        }
    }
}

// ---------------- vectorized fp32 -> (hi, lo) bf16 split ----------------
__device__ __forceinline__ uint32_t pack_hi2(float a, float b, float& la, float& lb) {
    bf16 ha = __float2bfloat16(a), hb = __float2bfloat16(b);
    la = a - __bfloat162float(ha);
    lb = b - __bfloat162float(hb);
    return (uint32_t)__bfloat16_as_ushort(ha) | ((uint32_t)__bfloat16_as_ushort(hb) << 16);
}
__device__ __forceinline__ uint32_t pack2(float a, float b) {
    return (uint32_t)__bfloat16_as_ushort(__float2bfloat16(a)) |
           ((uint32_t)__bfloat16_as_ushort(__float2bfloat16(b)) << 16);
}

__global__ void split_kernel(const float* __restrict__ x, bf16* __restrict__ hi,
                             bf16* __restrict__ lo, size_t n4)
{
    size_t i = (size_t)blockIdx.x * blockDim.x + threadIdx.x;
    if (i >= n4) return;
    float4 v = reinterpret_cast<const float4*>(x)[i];
    float lx, ly, lz, lw;
    uint2 h;
    h.x = pack_hi2(v.x, v.y, lx, ly);
    h.y = pack_hi2(v.z, v.w, lz, lw);
    uint2 l = { pack2(lx, ly), pack2(lz, lw) };
    reinterpret_cast<uint2*>(hi)[i] = h;
    reinterpret_cast<uint2*>(lo)[i] = l;
}

// ---------------- block reduction helpers ----------------
__device__ __forceinline__ float blk_reduce(float v, bool do_max, float* sred,
                                            int tid, int lane, int wid) {
    #pragma unroll
    for (int o = 16; o > 0; o >>= 1) {
        float t = __shfl_xor_sync(0xffffffffu, v, o);
        v = do_max ? fmaxf(v, t) : (v + t);
    }
    if (lane == 0) sred[wid] = v;
    __syncthreads();
    if (tid == 0) {
        float r = sred[0];
        #pragma unroll
        for (int w = 1; w < 8; ++w) r = do_max ? fmaxf(r, sred[w]) : (r + sred[w]);
        sred[8] = r;
    }
    __syncthreads();
    float r = sred[8];
    __syncthreads();
    return r;
}

// ---------------- RMSNorm + RoPE for Q -> split planes ----------------
__global__ __launch_bounds__(256)
void q_norm_rope_kernel(const float* __restrict__ qkv,
                        const float* __restrict__ cosb, const float* __restrict__ sinb,
                        const float* __restrict__ qw,
                        bf16* __restrict__ qh, bf16* __restrict__ ql)
{
    const int s = blockIdx.x, h = blockIdx.y, d = threadIdx.x;
    const int lane = d & 31, wid = d >> 5;
    float x = qkv[(size_t)s * NQKV + h * 512 + d];
    __shared__ float sred[9];
    __shared__ float xs[256];
    float r = blk_reduce(x * x, false, sred, d, lane, wid);
    r = rsqrtf(r * (1.f / HD) + EPSV);
    float xn = x * r * (1.f + qw[d]);
    xs[d] = xn;
    __syncthreads();
    float o = xn;
    if (d < RD) {
        float rot = (d < RD / 2) ? -xs[d + RD / 2] : xs[d - RD / 2];
        o = xn * cosb[(size_t)s * RD + d] + rot * sinb[(size_t)s * RD + d];
    }
    size_t idx = ((size_t)h * SEQ + s) * HD + d;
    bf16 hv = __float2bfloat16(o);
    qh[idx] = hv;
    ql[idx] = __float2bfloat16(o - __bfloat162float(hv));
}

// ---------------- RMSNorm + RoPE for K; caches + split planes ----------------
__global__ __launch_bounds__(256)
void kv_norm_rope_kernel(const float* __restrict__ qkv,
                         const float* __restrict__ cosb, const float* __restrict__ sinb,
                         const float* __restrict__ kw,
                         float* __restrict__ kcache, float* __restrict__ vcache,
                         bf16* __restrict__ kh, bf16* __restrict__ kl,
                         bf16* __restrict__ vTh, bf16* __restrict__ vTl)
{
    const int s = blockIdx.x, kv = blockIdx.y, d = threadIdx.x;
    const int lane = d & 31, wid = d >> 5;
    float x = qkv[(size_t)s * NQKV + 8192 + kv * 256 + d];
    float v = qkv[(size_t)s * NQKV + 8704 + kv * 256 + d];
    __shared__ float sred[9];
    __shared__ float xs[256];
    float r = blk_reduce(x * x, false, sred, d, lane, wid);
    r = rsqrtf(r * (1.f / HD) + EPSV);
    float xn = x * r * (1.f + kw[d]);
    xs[d] = xn;
    __syncthreads();
    float o = xn;
    if (d < RD) {
        float rot = (d < RD / 2) ? -xs[d + RD / 2] : xs[d - RD / 2];
        o = xn * cosb[(size_t)s * RD + d] + rot * sinb[(size_t)s * RD + d];
    }
    size_t cidx = ((size_t)kv * MAXS + s) * HD + d;
    kcache[cidx] = o;
    vcache[cidx] = v;
    size_t kidx = ((size_t)kv * SEQ + s) * HD + d;
    bf16 khv = __float2bfloat16(o);
    kh[kidx] = khv;
    kl[kidx] = __float2bfloat16(o - __bfloat162float(khv));
    size_t vidx = ((size_t)kv * HD + d) * SEQ + s;   // transposed
    bf16 vhv = __float2bfloat16(v);
    vTh[vidx] = vhv;
    vTl[vidx] = __float2bfloat16(v - __bfloat162float(vhv));
}

// ---------------- zero pad caches rows SEQ..MAXS ----------------
__global__ void zero_pad_kernel(float* __restrict__ kcache, float* __restrict__ vcache)
{
    size_t idx = (size_t)blockIdx.x * blockDim.x + threadIdx.x;
    const size_t per_kv = (size_t)(MAXS - SEQ) * HD;
    if (idx >= (size_t)NKV * per_kv) return;
    size_t kv = idx / per_kv, rem = idx - kv * per_kv;
    size_t off = kv * (size_t)MAXS * HD + (size_t)SEQ * HD + rem;
    kcache[off] = 0.f;
    vcache[off] = 0.f;
}

// ---------------- causal softmax (register row) -> split P planes ----------------
__global__ __launch_bounds__(256)
void softmax_kernel(const float* __restrict__ scores,
                    bf16* __restrict__ ph, bf16* __restrict__ pl)
{
    const int i = blockIdx.x, h = blockIdx.y, tid = threadIdx.x;
    const int lane = tid & 31, wid = tid >> 5;
    const float* row = scores + ((size_t)h * SEQ + i) * SEQ;
    bf16* prh = ph + ((size_t)h * SEQ + i) * SEQ;
    bf16* prl = pl + ((size_t)h * SEQ + i) * SEQ;
    const int n = i + 1;
    const int end = ((i >> 7) + 1) << 7;
    const int j0 = tid * 8;
    __shared__ float sred[9];

    float v[8];
    if (j0 < end) {
        float4 a = *reinterpret_cast<const float4*>(row + j0);
        float4 b = *reinterpret_cast<const float4*>(row + j0 + 4);
        v[0]=a.x; v[1]=a.y; v[2]=a.z; v[3]=a.w;
        v[4]=b.x; v[5]=b.y; v[6]=b.z; v[7]=b.w;
    } else {
        #pragma unroll
        for (int e = 0; e < 8; ++e) v[e] = -1e30f;
    }

    float m = -1e30f;
    #pragma unroll
    for (int e = 0; e < 8; ++e) if (j0 + e < n) m = fmaxf(m, v[e]);
    m = blk_reduce(m, true, sred, tid, lane, wid);

    float sum = 0.f;
    #pragma unroll
    for (int e = 0; e < 8; ++e) {
        float p = (j0 + e < n) ? __expf(v[e] - m) : 0.f;
        v[e] = p;
        sum += p;
    }
    sum = blk_reduce(sum, false, sred, tid, lane, wid);
    const float inv = 1.f / sum;

    if (j0 < end) {
        uint4 hh, ll;
        float lo[8];
        float p0 = v[0]*inv, p1 = v[1]*inv, p2 = v[2]*inv, p3 = v[3]*inv;
        float p4 = v[4]*inv, p5 = v[5]*inv, p6 = v[6]*inv, p7 = v[7]*inv;
        hh.x = pack_hi2(p0, p1, lo[0], lo[1]);
        hh.y = pack_hi2(p2, p3, lo[2], lo[3]);
        hh.z = pack_hi2(p4, p5, lo[4], lo[5]);
        hh.w = pack_hi2(p6, p7, lo[6], lo[7]);
        ll.x = pack2(lo[0], lo[1]); ll.y = pack2(lo[2], lo[3]);
        ll.z = pack2(lo[4], lo[5]); ll.w = pack2(lo[6], lo[7]);
        *reinterpret_cast<uint4*>(prh + j0) = hh;
        *reinterpret_cast<uint4*>(prl + j0) = ll;
    }
}

// ---------------- gating (x4 vectorized) -> split planes ----------------
__global__ void gate_kernel(const float* __restrict__ attn, const float* __restrict__ qkv,
                            bf16* __restrict__ gh, bf16* __restrict__ gl)
{
    size_t idx = (size_t)blockIdx.x * blockDim.x + threadIdx.x;   // quad index
    if (idx >= (size_t)SEQ * NH * HD / 4) return;
    int s = (int)(idx >> 10);
    int r = (int)(idx & 1023);
    int h = r >> 6, dq = (r & 63) * 4;
    float4 a = *reinterpret_cast<const float4*>(&attn[((size_t)h * SEQ + s) * HD + dq]);
    float4 g = *reinterpret_cast<const float4*>(&qkv[(size_t)s * NQKV + h * 512 + 256 + dq]);
    float o0 = a.x * (1.f / (1.f + __expf(-g.x)));
    float o1 = a.y * (1.f / (1.f + __expf(-g.y)));
    float o2 = a.z * (1.f / (1.f + __expf(-g.z)));
    float o3 = a.w * (1.f / (1.f + __expf(-g.w)));
    float l0, l1, l2, l3;
    uint2 hh = { pack_hi2(o0, o1, l0, l1), pack_hi2(o2, o3, l2, l3) };
    uint2 ll = { pack2(l0, l1), pack2(l2, l3) };
    size_t o = (size_t)s * (NH * HD) + h * HD + dq;
    *reinterpret_cast<uint2*>(gh + o) = hh;
    *reinterpret_cast<uint2*>(gl + o) = ll;
}

// ---------------- launch ----------------
extern "C" void kernel_launch(void* const* d_in, const int* in_sizes, int n_in,
                              void* d_out, int out_size)
{
    const float* hidden = (const float*)d_in[0];
    const float* cosb   = (const float*)d_in[1];
    const float* sinb   = (const float*)d_in[2];
    const float* q_w    = (const float*)d_in[3];
    const float* k_w    = (const float*)d_in[4];
    const float* v_w    = (const float*)d_in[5];
    const float* o_w    = (const float*)d_in[6];
    const float* qnw    = (const float*)d_in[7];
    const float* knw    = (const float*)d_in[8];

    float* hidden_out = (float*)d_out;
    float* kcache = hidden_out + (size_t)SEQ * HID;
    float* vcache = kcache + (size_t)NKV * MAXS * HD;

    float *qkv, *sc, *at;
    bf16 *hidh, *hidl, *wh, *wl, *owh, *owl;
    bf16 *qh, *ql, *kh, *kl, *vTh, *vTl, *ph, *pl, *gth, *gtl;
    cudaGetSymbolAddress((void**)&qkv, g_qkv);
    cudaGetSymbolAddress((void**)&sc, g_scores);
    cudaGetSymbolAddress((void**)&at, g_attn);
    cudaGetSymbolAddress((void**)&hidh, g_hid_h); cudaGetSymbolAddress((void**)&hidl, g_hid_l);
    cudaGetSymbolAddress((void**)&wh, g_wqkv_h);  cudaGetSymbolAddress((void**)&wl, g_wqkv_l);
    cudaGetSymbolAddress((void**)&owh, g_ow_h);   cudaGetSymbolAddress((void**)&owl, g_ow_l);
    cudaGetSymbolAddress((void**)&qh, g_q_h);     cudaGetSymbolAddress((void**)&ql, g_q_l);
    cudaGetSymbolAddress((void**)&kh, g_k_h);     cudaGetSymbolAddress((void**)&kl, g_k_l);
    cudaGetSymbolAddress((void**)&vTh, g_vT_h);   cudaGetSymbolAddress((void**)&vTl, g_vT_l);
    cudaGetSymbolAddress((void**)&ph, g_p_h);     cudaGetSymbolAddress((void**)&pl, g_p_l);
    cudaGetSymbolAddress((void**)&gth, g_gt_h);   cudaGetSymbolAddress((void**)&gtl, g_gt_l);

    cudaFuncSetAttribute(gemm_hmma, cudaFuncAttributeMaxDynamicSharedMemorySize, GSMEM);

    dim3 blk(256);
    dim3 gblk(512);
    auto nb4 = [](size_t n) { return (unsigned)((n / 4 + 255) / 256); };

    // splits (weights q|k|v concatenated into one [9216, 2048] plane pair)
    split_kernel<<<nb4((size_t)SEQ * HID), blk>>>(hidden, hidh, hidl, (size_t)SEQ * HID / 4);
    split_kernel<<<nb4((size_t)8192 * HID), blk>>>(q_w, wh, wl, (size_t)8192 * HID / 4);
    split_kernel<<<nb4((size_t)512 * HID), blk>>>(k_w, wh + (size_t)8192 * HID,
                                                  wl + (size_t)8192 * HID, (size_t)512 * HID / 4);
    split_kernel<<<nb4((size_t)512 * HID), blk>>>(v_w, wh + (size_t)8704 * HID,
                                                  wl + (size_t)8704 * HID, (size_t)512 * HID / 4);
    split_kernel<<<nb4((size_t)HID * NH*HD), blk>>>(o_w, owh, owl, (size_t)HID * NH*HD / 4);

    // fused qkv projection: [2048 x 9216]
    gemm_hmma<<<dim3(NQKV/128, SEQ/128, 1), gblk, GSMEM>>>(
        hidh, hidl, wh, wl, qkv, HID, HID, HID, NQKV, 0, 0, 0, 1, 1.f, 0);

    // norms + rope + caches
    q_norm_rope_kernel<<<dim3(SEQ, NH), blk>>>(qkv, cosb, sinb, qnw, qh, ql);
    kv_norm_rope_kernel<<<dim3(SEQ, NKV), blk>>>(qkv, cosb, sinb, knw,
                                                 kcache, vcache, kh, kl, vTh, vTl);
    zero_pad_kernel<<<(unsigned)(((size_t)NKV * (MAXS - SEQ) * HD + 255) / 256), blk>>>(kcache, vcache);

    // scores = Q @ K^T * scale (causal block skip)
    gemm_hmma<<<dim3(SEQ/128, SEQ/128, NH), gblk, GSMEM>>>(
        qh, ql, kh, kl, sc, HD, HD, HD, SEQ,
        (long long)SEQ * HD, (long long)SEQ * HD, (long long)SEQ * SEQ, GROUPS,
        ATT_SCALE, 1);

    softmax_kernel<<<dim3(SEQ, NH), blk>>>(sc, ph, pl);

    // attn = P @ V (causal K limit); B = V^T [d][s]
    gemm_hmma<<<dim3(HD/128, SEQ/128, NH), gblk, GSMEM>>>(
        ph, pl, vTh, vTl, at, SEQ, SEQ, SEQ, HD,
        (long long)SEQ * SEQ, (long long)HD * SEQ, (long long)SEQ * HD, GROUPS,
        1.f, 2);

    gate_kernel<<<(unsigned)(((size_t)SEQ * NH * HD / 4 + 255) / 256), blk>>>(at, qkv, gth, gtl);

    // hidden_out = gated @ o_w^T
    gemm_hmma<<<dim3(HID/128, SEQ/128, 1), gblk, GSMEM>>>(
        gth, gtl, owh, owl, hidden_out, NH*HD, NH*HD, NH*HD, HID, 0, 0, 0, 1, 1.f, 0);
}